// round 2
// baseline (speedup 1.0000x reference)
#include <cuda_runtime.h>

// Denoise_17669495455833 — batched 1-D FISTA QP:
//   min ||y-x||^2 + LAM*||diff(x,2)||^2  s.t. 0 <= x <= y, per row of 512.
// Two identical passes (reference's "column pass" re-solves rows).
// One warp per row, 16 elems/thread, all state in registers, halos via shfl.

#define LAM_F    10.0f
#define N_ITERS  100
#define ROWLEN   512
#define EPT      16                 // elements per thread (512 / 32 lanes)
#define TPB      256                // 8 warps (rows) per block

__device__ __forceinline__ void fista_pass(const float y[EPT], float x[EPT], int lane)
{
    const float step = 1.0f / (2.0f * (1.0f + 16.0f * LAM_F));   // 1/322
    const float ca   = 1.0f - 2.0f * step;                       // z coeff
    const float cb   = 2.0f * step;                              // y coeff
    const float cc   = 2.0f * LAM_F * step;                      // DtD coeff

    float z[EPT];
#pragma unroll
    for (int i = 0; i < EPT; ++i) {
        x[i] = fminf(fmaxf(y[i], 0.0f), y[i]);                   // proj(y)
        z[i] = x[i];
    }

    float t = 1.0f;
    for (int it = 0; it < N_ITERS; ++it) {
        // halo z-values from next lane (z[16], z[17])
        float zn0 = __shfl_down_sync(0xffffffffu, z[0], 1);
        float zn1 = __shfl_down_sync(0xffffffffu, z[1], 1);

        // d[j] = z[j+2] - 2 z[j+1] + z[j], valid for global j <= ROWLEN-3
        float d[EPT];
#pragma unroll
        for (int k = 0; k < EPT - 2; ++k)
            d[k] = fmaf(-2.0f, z[k + 1], z[k + 2]) + z[k];
        d[EPT - 2] = fmaf(-2.0f, z[EPT - 1], zn0) + z[EPT - 2];
        d[EPT - 1] = fmaf(-2.0f, zn0, zn1) + z[EPT - 1];
        if (lane == 31) { d[EPT - 2] = 0.0f; d[EPT - 1] = 0.0f; } // j = n-2, n-1 -> 0

        // halo d-values from previous lane (d[-1], d[-2])
        float dm1 = __shfl_up_sync(0xffffffffu, d[EPT - 1], 1);
        float dm2 = __shfl_up_sync(0xffffffffu, d[EPT - 2], 1);
        if (lane == 0) { dm1 = 0.0f; dm2 = 0.0f; }

        // momentum coefficient (identical across all threads)
        float tn = 0.5f * (1.0f + sqrtf(fmaf(4.0f * t, t, 1.0f)));
        float ck = (t - 1.0f) / tn;
        t = tn;

#pragma unroll
        for (int i = 0; i < EPT; ++i) {
            float di1 = (i >= 1) ? d[i - 1] : dm1;
            float di2 = (i >= 2) ? d[i - 2] : ((i == 1) ? dm1 : dm2);
            // DtD(z)[i] = d[i] - 2 d[i-1] + d[i-2]
            float o  = fmaf(-2.0f, di1, d[i]) + di2;
            // z - step*g  =  ca*z + cb*y - cc*o
            float v  = fmaf(ca, z[i], fmaf(cb, y[i], -cc * o));
            float xn = fminf(fmaxf(v, 0.0f), y[i]);               // proj onto [0, y]
            z[i] = fmaf(ck, xn - x[i], xn);                       // momentum step
            x[i] = xn;
        }
    }
}

__global__ void __launch_bounds__(TPB, 2)
denoise_fista_kernel(const float* __restrict__ in, float* __restrict__ out, int nrows)
{
    const int warp = blockIdx.x * (TPB / 32) + (threadIdx.x >> 5);
    const int lane = threadIdx.x & 31;
    if (warp >= nrows) return;

    const float4* src = reinterpret_cast<const float4*>(in + (size_t)warp * ROWLEN + lane * EPT);
    float y[EPT];
    {
        float4 a = src[0], b = src[1], c = src[2], d4 = src[3];
        y[0] = a.x;  y[1] = a.y;  y[2]  = a.z;  y[3]  = a.w;
        y[4] = b.x;  y[5] = b.y;  y[6]  = b.z;  y[7]  = b.w;
        y[8] = c.x;  y[9] = c.y;  y[10] = c.z;  y[11] = c.w;
        y[12] = d4.x; y[13] = d4.y; y[14] = d4.z; y[15] = d4.w;
    }

    float x[EPT];
    fista_pass(y, x, lane);          // pass 1: y = input

    float y2[EPT];
#pragma unroll
    for (int i = 0; i < EPT; ++i) y2[i] = x[i];
    fista_pass(y2, x, lane);         // pass 2: y = pass-1 output

    float4* dst = reinterpret_cast<float4*>(out + (size_t)warp * ROWLEN + lane * EPT);
    float4 a, b, c, d4;
    a.x = x[0];  a.y = x[1];  a.z = x[2];   a.w = x[3];
    b.x = x[4];  b.y = x[5];  b.z = x[6];   b.w = x[7];
    c.x = x[8];  c.y = x[9];  c.z = x[10];  c.w = x[11];
    d4.x = x[12]; d4.y = x[13]; d4.z = x[14]; d4.w = x[15];
    dst[0] = a; dst[1] = b; dst[2] = c; dst[3] = d4;
}

extern "C" void kernel_launch(void* const* d_in, const int* in_sizes, int n_in,
                              void* d_out, int out_size)
{
    const float* in  = (const float*)d_in[0];
    float*       out = (float*)d_out;
    const int nrows  = in_sizes[0] / ROWLEN;          // 32*512 = 16384
    const int rows_per_block = TPB / 32;              // 8
    const int grid = (nrows + rows_per_block - 1) / rows_per_block;
    denoise_fista_kernel<<<grid, TPB>>>(in, out, nrows);
}

// round 5
// speedup vs baseline: 1.2204x; 1.2204x over previous
#include <cuda_runtime.h>

// Denoise_17669495455833 — batched 1-D FISTA QP, 2 passes, one warp per 512-row.
// R2: fused 5-point stencil (ghost-point boundaries), constexpr ck table,
//     FFMA-imm coefficients, no d[] staging array.

#define N_ITERS  100
#define ROWLEN   512
#define EPT      16
#define TPB      256

// step = 1/(2(1+16*10)) = 1/322 ; gradient step coefficients (compile-time)
constexpr float STEP = 1.0f / 322.0f;
constexpr float CB   = 2.0f * STEP;            // y coefficient
constexpr float CC   = 20.0f * STEP;           // 2*LAM*step
constexpr float C0   = -CC;                    // z[i+-2]
constexpr float C1   = 4.0f * CC;              // z[i+-1]
constexpr float C2   = (1.0f - 2.0f * STEP) - 6.0f * CC;   // z[i]

// ---- compile-time FISTA momentum coefficients ck = (t-1)/t_next ----
constexpr double csqrt(double x) {
    double g = x > 1.0 ? x : 1.0;
    for (int i = 0; i < 48; ++i) g = 0.5 * (g + x / g);
    return g;
}
struct CkTable {
    float v[N_ITERS];
    constexpr CkTable() : v{} {
        double t = 1.0;
        for (int i = 0; i < N_ITERS; ++i) {
            double tn = 0.5 * (1.0 + csqrt(1.0 + 4.0 * t * t));
            v[i] = (float)((t - 1.0) / tn);
            t = tn;
        }
    }
};
__constant__ CkTable CKTAB = CkTable();

__device__ __forceinline__ void fista_pass(const float y[EPT], const float yc[EPT],
                                           float x[EPT], int lane)
{
    float z[EPT];
#pragma unroll
    for (int i = 0; i < EPT; ++i) {
        x[i] = fminf(fmaxf(y[i], 0.0f), y[i]);   // proj(y)
        z[i] = x[i];
    }

    const bool L = (lane == 0), R = (lane == 31);

#pragma unroll 1
    for (int it = 0; it < N_ITERS; ++it) {
        const float ck = CKTAB.v[it];

        // halos (old z values; all lanes still converged here)
        float zr1 = __shfl_down_sync(0xffffffffu, z[0], 1);
        float zr2 = __shfl_down_sync(0xffffffffu, z[1], 1);
        float zl1 = __shfl_up_sync  (0xffffffffu, z[EPT - 1], 1);
        float zl2 = __shfl_up_sync  (0xffffffffu, z[EPT - 2], 1);

        // ghost points: linear extrapolation reproduces exact DtD boundary rows
        {
            float a = z[0] - z[1];
            float g1 = z[0] + a;          // 2 z0 - z1
            float g2 = g1 + a;            // 3 z0 - 2 z1
            zl1 = L ? g1 : zl1;
            zl2 = L ? g2 : zl2;
            float b = z[EPT - 1] - z[EPT - 2];
            float h1 = z[EPT - 1] + b;    // 2 z15 - z14
            float h2 = h1 + b;            // 3 z15 - 2 z14
            zr1 = R ? h1 : zr1;
            zr2 = R ? h2 : zr2;
        }

        // fused update: v = cb*y + c0*z[i-2] + c1*z[i-1] + c2*z[i] + c1*z[i+1] + c0*z[i+2]
        float om2 = zl2, om1 = zl1;       // rolling old z[i-2], z[i-1]
#pragma unroll
        for (int i = 0; i < EPT; ++i) {
            float cur = z[i];
            float p1 = (i < EPT - 1) ? z[i + 1] : zr1;
            float p2 = (i < EPT - 2) ? z[i + 2] : ((i == EPT - 2) ? zr1 : zr2);

            float v = fmaf(C0, om2, yc[i]);
            v = fmaf(C1, om1, v);
            v = fmaf(C2, cur, v);
            v = fmaf(C1, p1,  v);
            v = fmaf(C0, p2,  v);

            float xn = fminf(fmaxf(v, 0.0f), y[i]);   // proj onto [0, y]
            z[i] = fmaf(ck, xn - x[i], xn);           // momentum step
            x[i] = xn;

            om2 = om1; om1 = cur;
        }
    }
}

__global__ void __launch_bounds__(TPB, 2)
denoise_fista_kernel(const float* __restrict__ in, float* __restrict__ out, int nrows)
{
    const int warp = blockIdx.x * (TPB / 32) + (threadIdx.x >> 5);
    const int lane = threadIdx.x & 31;
    if (warp >= nrows) return;

    const float4* src = reinterpret_cast<const float4*>(in + (size_t)warp * ROWLEN + lane * EPT);
    float y[EPT], yc[EPT];
    {
        float4 a = src[0], b = src[1], c = src[2], d4 = src[3];
        y[0] = a.x;  y[1] = a.y;  y[2]  = a.z;  y[3]  = a.w;
        y[4] = b.x;  y[5] = b.y;  y[6]  = b.z;  y[7]  = b.w;
        y[8] = c.x;  y[9] = c.y;  y[10] = c.z;  y[11] = c.w;
        y[12] = d4.x; y[13] = d4.y; y[14] = d4.z; y[15] = d4.w;
    }
#pragma unroll
    for (int i = 0; i < EPT; ++i) yc[i] = CB * y[i];

    float x[EPT];
    fista_pass(y, yc, x, lane);        // pass 1: y = input

    float y2[EPT], yc2[EPT];
#pragma unroll
    for (int i = 0; i < EPT; ++i) { y2[i] = x[i]; yc2[i] = CB * x[i]; }
    fista_pass(y2, yc2, x, lane);      // pass 2: y = pass-1 output

    float4* dst = reinterpret_cast<float4*>(out + (size_t)warp * ROWLEN + lane * EPT);
    float4 a, b, c, d4;
    a.x = x[0];  a.y = x[1];  a.z = x[2];   a.w = x[3];
    b.x = x[4];  b.y = x[5];  b.z = x[6];   b.w = x[7];
    c.x = x[8];  c.y = x[9];  c.z = x[10];  c.w = x[11];
    d4.x = x[12]; d4.y = x[13]; d4.z = x[14]; d4.w = x[15];
    dst[0] = a; dst[1] = b; dst[2] = c; dst[3] = d4;
}

extern "C" void kernel_launch(void* const* d_in, const int* in_sizes, int n_in,
                              void* d_out, int out_size)
{
    const float* in  = (const float*)d_in[0];
    float*       out = (float*)d_out;
    const int nrows  = in_sizes[0] / ROWLEN;            // 16384
    const int rows_per_block = TPB / 32;
    const int grid = (nrows + rows_per_block - 1) / rows_per_block;
    denoise_fista_kernel<<<grid, TPB>>>(in, out, nrows);
}

// round 6
// speedup vs baseline: 1.4847x; 1.2166x over previous
#include <cuda_runtime.h>

// Denoise_17669495455833 — batched 1-D FISTA QP, 2 passes, one warp per 512-row.
// R3: f32x2 packed math (FFMA2). Interleaved packing P_j = (z[j], z[j+8]) keeps
//     stencil shifts pair-aligned; only 4 seam pairs repacked per iteration.

#define N_ITERS  100
#define ROWLEN   512
#define EPT      16
#define NP       8            // packed pairs per thread
#define TPB      256

constexpr float STEP = 1.0f / 322.0f;
constexpr float CBc  = 2.0f * STEP;                         // y coefficient
constexpr float CCc  = 20.0f * STEP;
constexpr float C0c  = -CCc;                                // z[i+-2]
constexpr float C1c  = 4.0f * CCc;                          // z[i+-1]
constexpr float C2c  = (1.0f - 2.0f * STEP) - 6.0f * CCc;   // z[i]

// ---- compile-time FISTA momentum coefficients ck = (t-1)/t_next ----
constexpr double csqrt(double x) {
    double g = x > 1.0 ? x : 1.0;
    for (int i = 0; i < 48; ++i) g = 0.5 * (g + x / g);
    return g;
}
struct CkTable {
    float v[N_ITERS];
    constexpr CkTable() : v{} {
        double t = 1.0;
        for (int i = 0; i < N_ITERS; ++i) {
            double tn = 0.5 * (1.0 + csqrt(1.0 + 4.0 * t * t));
            v[i] = (float)((t - 1.0) / tn);
            t = tn;
        }
    }
};
__constant__ CkTable CKTAB = CkTable();

using u64 = unsigned long long;

__device__ __forceinline__ u64 pk2(float lo, float hi) {
    u64 r; asm("mov.b64 %0,{%1,%2};" : "=l"(r) : "f"(lo), "f"(hi)); return r;
}
__device__ __forceinline__ void upk2(u64 v, float& lo, float& hi) {
    asm("mov.b64 {%0,%1},%2;" : "=f"(lo), "=f"(hi) : "l"(v));
}
__device__ __forceinline__ u64 f2fma(u64 a, u64 b, u64 c) {   // a*b + c (packed)
    u64 d; asm("fma.rn.f32x2 %0,%1,%2,%3;" : "=l"(d) : "l"(a), "l"(b), "l"(c)); return d;
}

__device__ __forceinline__ void fista_pass(const float ys[EPT], const u64 ycP[NP],
                                           u64 xP[NP], int lane)
{
    u64 zP[NP];
#pragma unroll
    for (int j = 0; j < NP; ++j) {
        float a = fminf(fmaxf(ys[j],     0.0f), ys[j]);
        float b = fminf(fmaxf(ys[j + 8], 0.0f), ys[j + 8]);
        xP[j] = pk2(a, b);
        zP[j] = xP[j];
    }

    const bool L = (lane == 0), R = (lane == 31);
    const u64 C0P = pk2(C0c, C0c);
    const u64 C1P = pk2(C1c, C1c);
    const u64 C2P = pk2(C2c, C2c);
    const u64 M1P = pk2(-1.0f, -1.0f);

#pragma unroll 1
    for (int it = 0; it < N_ITERS; ++it) {
        const float ck  = CKTAB.v[it];
        const u64   ckP = pk2(ck, ck);

        // scalar views of the z values needed for halos / ghosts / seams
        float z0, z8, z1, z9, z6, z14, z7, z15;
        upk2(zP[0], z0, z8);
        upk2(zP[1], z1, z9);
        upk2(zP[6], z6, z14);
        upk2(zP[7], z7, z15);

        float zm1  = __shfl_up_sync  (0xffffffffu, z15, 1);   // z[-1]
        float zm2  = __shfl_up_sync  (0xffffffffu, z14, 1);   // z[-2]
        float zp16 = __shfl_down_sync(0xffffffffu, z0,  1);   // z[16]
        float zp17 = __shfl_down_sync(0xffffffffu, z1,  1);   // z[17]

        // ghost points (linear extrapolation == exact DtD boundary rows)
        {
            float a  = z0 - z1;
            float g1 = z0 + a;
            float g2 = g1 + a;
            if (L) { zm1 = g1; zm2 = g2; }
            float b  = z15 - z14;
            float h1 = z15 + b;
            float h2 = h1 + b;
            if (R) { zp16 = h1; zp17 = h2; }
        }

        // extended pair array: PP[j+2] covers pair positions j = -2 .. 9
        u64 PP[NP + 4];
        PP[0] = pk2(zm2, z6);        // (z[-2], z[6])
        PP[1] = pk2(zm1, z7);        // (z[-1], z[7])
#pragma unroll
        for (int j = 0; j < NP; ++j) PP[j + 2] = zP[j];
        PP[10] = pk2(z8, zp16);      // (z[8],  z[16])
        PP[11] = pk2(z9, zp17);      // (z[9],  z[17])

#pragma unroll
        for (int j = 0; j < NP; ++j) {
            u64 v = f2fma(C0P, PP[j],     ycP[j]);
            v     = f2fma(C1P, PP[j + 1], v);
            v     = f2fma(C2P, PP[j + 2], v);
            v     = f2fma(C1P, PP[j + 3], v);
            v     = f2fma(C0P, PP[j + 4], v);

            float lo, hi;
            upk2(v, lo, hi);
            lo = fminf(fmaxf(lo, 0.0f), ys[j]);
            hi = fminf(fmaxf(hi, 0.0f), ys[j + 8]);
            u64 xn = pk2(lo, hi);

            u64 d  = f2fma(xP[j], M1P, xn);   // xn - x_old
            zP[j]  = f2fma(ckP, d, xn);       // momentum step
            xP[j]  = xn;
        }
    }
}

__global__ void __launch_bounds__(TPB, 2)
denoise_fista_kernel(const float* __restrict__ in, float* __restrict__ out, int nrows)
{
    const int warp = blockIdx.x * (TPB / 32) + (threadIdx.x >> 5);
    const int lane = threadIdx.x & 31;
    if (warp >= nrows) return;

    const float4* src = reinterpret_cast<const float4*>(in + (size_t)warp * ROWLEN + lane * EPT);
    float ys[EPT];
    {
        float4 a = src[0], b = src[1], c = src[2], d4 = src[3];
        ys[0] = a.x;  ys[1] = a.y;  ys[2]  = a.z;  ys[3]  = a.w;
        ys[4] = b.x;  ys[5] = b.y;  ys[6]  = b.z;  ys[7]  = b.w;
        ys[8] = c.x;  ys[9] = c.y;  ys[10] = c.z;  ys[11] = c.w;
        ys[12] = d4.x; ys[13] = d4.y; ys[14] = d4.z; ys[15] = d4.w;
    }

    u64 ycP[NP];
#pragma unroll
    for (int j = 0; j < NP; ++j) ycP[j] = pk2(CBc * ys[j], CBc * ys[j + 8]);

    u64 xP[NP];
    fista_pass(ys, ycP, xP, lane);        // pass 1: y = input

    float y2[EPT];
    u64 ycP2[NP];
#pragma unroll
    for (int j = 0; j < NP; ++j) {
        float lo, hi;
        upk2(xP[j], lo, hi);
        y2[j] = lo; y2[j + 8] = hi;
        ycP2[j] = pk2(CBc * lo, CBc * hi);
    }
    fista_pass(y2, ycP2, xP, lane);       // pass 2: y = pass-1 output

    float xo[EPT];
#pragma unroll
    for (int j = 0; j < NP; ++j) {
        float lo, hi;
        upk2(xP[j], lo, hi);
        xo[j] = lo; xo[j + 8] = hi;
    }

    float4* dst = reinterpret_cast<float4*>(out + (size_t)warp * ROWLEN + lane * EPT);
    float4 a, b, c, d4;
    a.x = xo[0];  a.y = xo[1];  a.z = xo[2];   a.w = xo[3];
    b.x = xo[4];  b.y = xo[5];  b.z = xo[6];   b.w = xo[7];
    c.x = xo[8];  c.y = xo[9];  c.z = xo[10];  c.w = xo[11];
    d4.x = xo[12]; d4.y = xo[13]; d4.z = xo[14]; d4.w = xo[15];
    dst[0] = a; dst[1] = b; dst[2] = c; dst[3] = d4;
}

extern "C" void kernel_launch(void* const* d_in, const int* in_sizes, int n_in,
                              void* d_out, int out_size)
{
    const float* in  = (const float*)d_in[0];
    float*       out = (float*)d_out;
    const int nrows  = in_sizes[0] / ROWLEN;            // 16384
    const int rows_per_block = TPB / 32;
    const int grid = (nrows + rows_per_block - 1) / rows_per_block;
    denoise_fista_kernel<<<grid, TPB>>>(in, out, nrows);
}

// round 10
// speedup vs baseline: 1.5407x; 1.0378x over previous
#include <cuda_runtime.h>

// Denoise_17669495455833 — batched 1-D FISTA QP, 2 passes, one warp per 512-row.
// R4: same FFMA2 packed math as R3; occupancy 16 -> 20 warps/SM via
//     TPB=128 + __launch_bounds__(128,5) to cover SHFL/FFMA2 latency.

#define N_ITERS  100
#define ROWLEN   512
#define EPT      16
#define NP       8            // packed pairs per thread
#define TPB      128

constexpr float STEP = 1.0f / 322.0f;
constexpr float CBc  = 2.0f * STEP;                         // y coefficient
constexpr float CCc  = 20.0f * STEP;
constexpr float C0c  = -CCc;                                // z[i+-2]
constexpr float C1c  = 4.0f * CCc;                          // z[i+-1]
constexpr float C2c  = (1.0f - 2.0f * STEP) - 6.0f * CCc;   // z[i]

// ---- compile-time FISTA momentum coefficients ck = (t-1)/t_next ----
constexpr double csqrt(double x) {
    double g = x > 1.0 ? x : 1.0;
    for (int i = 0; i < 48; ++i) g = 0.5 * (g + x / g);
    return g;
}
struct CkTable {
    float v[N_ITERS];
    constexpr CkTable() : v{} {
        double t = 1.0;
        for (int i = 0; i < N_ITERS; ++i) {
            double tn = 0.5 * (1.0 + csqrt(1.0 + 4.0 * t * t));
            v[i] = (float)((t - 1.0) / tn);
            t = tn;
        }
    }
};
__constant__ CkTable CKTAB = CkTable();

using u64 = unsigned long long;

__device__ __forceinline__ u64 pk2(float lo, float hi) {
    u64 r; asm("mov.b64 %0,{%1,%2};" : "=l"(r) : "f"(lo), "f"(hi)); return r;
}
__device__ __forceinline__ void upk2(u64 v, float& lo, float& hi) {
    asm("mov.b64 {%0,%1},%2;" : "=f"(lo), "=f"(hi) : "l"(v));
}
__device__ __forceinline__ u64 f2fma(u64 a, u64 b, u64 c) {   // a*b + c (packed)
    u64 d; asm("fma.rn.f32x2 %0,%1,%2,%3;" : "=l"(d) : "l"(a), "l"(b), "l"(c)); return d;
}

__device__ __forceinline__ void fista_pass(const float ys[EPT], const u64 ycP[NP],
                                           u64 xP[NP], int lane)
{
    u64 zP[NP];
#pragma unroll
    for (int j = 0; j < NP; ++j) {
        float a = fminf(fmaxf(ys[j],     0.0f), ys[j]);
        float b = fminf(fmaxf(ys[j + 8], 0.0f), ys[j + 8]);
        xP[j] = pk2(a, b);
        zP[j] = xP[j];
    }

    const bool L = (lane == 0), R = (lane == 31);
    const u64 C0P = pk2(C0c, C0c);
    const u64 C1P = pk2(C1c, C1c);
    const u64 C2P = pk2(C2c, C2c);
    const u64 M1P = pk2(-1.0f, -1.0f);

#pragma unroll 1
    for (int it = 0; it < N_ITERS; ++it) {
        const float ck  = CKTAB.v[it];
        const u64   ckP = pk2(ck, ck);

        // scalar views of the z values needed for halos / ghosts / seams
        float z0, z8, z1, z9, z6, z14, z7, z15;
        upk2(zP[0], z0, z8);
        upk2(zP[1], z1, z9);
        upk2(zP[6], z6, z14);
        upk2(zP[7], z7, z15);

        float zm1  = __shfl_up_sync  (0xffffffffu, z15, 1);   // z[-1]
        float zm2  = __shfl_up_sync  (0xffffffffu, z14, 1);   // z[-2]
        float zp16 = __shfl_down_sync(0xffffffffu, z0,  1);   // z[16]
        float zp17 = __shfl_down_sync(0xffffffffu, z1,  1);   // z[17]

        // ghost points (linear extrapolation == exact DtD boundary rows)
        {
            float a  = z0 - z1;
            float g1 = z0 + a;
            float g2 = g1 + a;
            if (L) { zm1 = g1; zm2 = g2; }
            float b  = z15 - z14;
            float h1 = z15 + b;
            float h2 = h1 + b;
            if (R) { zp16 = h1; zp17 = h2; }
        }

        // extended pair array: PP[j+2] covers pair positions j = -2 .. 9
        u64 PP[NP + 4];
        PP[0] = pk2(zm2, z6);        // (z[-2], z[6])
        PP[1] = pk2(zm1, z7);        // (z[-1], z[7])
#pragma unroll
        for (int j = 0; j < NP; ++j) PP[j + 2] = zP[j];
        PP[10] = pk2(z8, zp16);      // (z[8],  z[16])
        PP[11] = pk2(z9, zp17);      // (z[9],  z[17])

#pragma unroll
        for (int j = 0; j < NP; ++j) {
            u64 v = f2fma(C0P, PP[j],     ycP[j]);
            v     = f2fma(C1P, PP[j + 1], v);
            v     = f2fma(C2P, PP[j + 2], v);
            v     = f2fma(C1P, PP[j + 3], v);
            v     = f2fma(C0P, PP[j + 4], v);

            float lo, hi;
            upk2(v, lo, hi);
            lo = fminf(fmaxf(lo, 0.0f), ys[j]);
            hi = fminf(fmaxf(hi, 0.0f), ys[j + 8]);
            u64 xn = pk2(lo, hi);

            u64 d  = f2fma(xP[j], M1P, xn);   // xn - x_old
            zP[j]  = f2fma(ckP, d, xn);       // momentum step
            xP[j]  = xn;
        }
    }
}

__global__ void __launch_bounds__(TPB, 5)
denoise_fista_kernel(const float* __restrict__ in, float* __restrict__ out, int nrows)
{
    const int warp = blockIdx.x * (TPB / 32) + (threadIdx.x >> 5);
    const int lane = threadIdx.x & 31;
    if (warp >= nrows) return;

    const float4* src = reinterpret_cast<const float4*>(in + (size_t)warp * ROWLEN + lane * EPT);
    float ys[EPT];
    {
        float4 a = src[0], b = src[1], c = src[2], d4 = src[3];
        ys[0] = a.x;  ys[1] = a.y;  ys[2]  = a.z;  ys[3]  = a.w;
        ys[4] = b.x;  ys[5] = b.y;  ys[6]  = b.z;  ys[7]  = b.w;
        ys[8] = c.x;  ys[9] = c.y;  ys[10] = c.z;  ys[11] = c.w;
        ys[12] = d4.x; ys[13] = d4.y; ys[14] = d4.z; ys[15] = d4.w;
    }

    u64 ycP[NP];
#pragma unroll
    for (int j = 0; j < NP; ++j) ycP[j] = pk2(CBc * ys[j], CBc * ys[j + 8]);

    u64 xP[NP];
    fista_pass(ys, ycP, xP, lane);        // pass 1: y = input

    float y2[EPT];
    u64 ycP2[NP];
#pragma unroll
    for (int j = 0; j < NP; ++j) {
        float lo, hi;
        upk2(xP[j], lo, hi);
        y2[j] = lo; y2[j + 8] = hi;
        ycP2[j] = pk2(CBc * lo, CBc * hi);
    }
    fista_pass(y2, ycP2, xP, lane);       // pass 2: y = pass-1 output

    float xo[EPT];
#pragma unroll
    for (int j = 0; j < NP; ++j) {
        float lo, hi;
        upk2(xP[j], lo, hi);
        xo[j] = lo; xo[j + 8] = hi;
    }

    float4* dst = reinterpret_cast<float4*>(out + (size_t)warp * ROWLEN + lane * EPT);
    float4 a, b, c, d4;
    a.x = xo[0];  a.y = xo[1];  a.z = xo[2];   a.w = xo[3];
    b.x = xo[4];  b.y = xo[5];  b.z = xo[6];   b.w = xo[7];
    c.x = xo[8];  c.y = xo[9];  c.z = xo[10];  c.w = xo[11];
    d4.x = xo[12]; d4.y = xo[13]; d4.z = xo[14]; d4.w = xo[15];
    dst[0] = a; dst[1] = b; dst[2] = c; dst[3] = d4;
}

extern "C" void kernel_launch(void* const* d_in, const int* in_sizes, int n_in,
                              void* d_out, int out_size)
{
    const float* in  = (const float*)d_in[0];
    float*       out = (float*)d_out;
    const int nrows  = in_sizes[0] / ROWLEN;            // 16384
    const int rows_per_block = TPB / 32;                // 4
    const int grid = (nrows + rows_per_block - 1) / rows_per_block;
    denoise_fista_kernel<<<grid, TPB>>>(in, out, nrows);
}